// round 2
// baseline (speedup 1.0000x reference)
#include <cuda_runtime.h>
#include <cuda_bf16.h>
#include <mma.h>

using namespace nvcuda;

// Problem constants (fixed shapes per reference setup_inputs)
#define NB   8      // batch
#define LQ   1024   // queries
#define CD   256    // d_model
#define NH   8      // heads
#define NPT  4      // points
#define HD   32     // head dim
#define HH   128
#define WWp  128
#define HWSZ (HH * WWp)

// ---------------- scratch (device globals; no allocations allowed) ----------
__device__ float  g_value[(size_t)NB * NH * HWSZ * HD];   // [b][h][y*W+x][d]  134 MB
__device__ float4 g_samp[(size_t)NB * LQ * NH * NPT];     // (x_pix, y_pix, attn_w, _)
__device__ float  g_S[(size_t)NB * LQ * CD];              // sampled [b][q][h*32+d]

// ---------------- kernel 1: offsets + attention weights + sample coords -----
__global__ void __launch_bounds__(128) k_offsets(
    const float* __restrict__ query,
    const float* __restrict__ refp,
    const float* __restrict__ Woff, const float* __restrict__ boff,
    const float* __restrict__ Wattn, const float* __restrict__ battn)
{
    __shared__ float sq[CD];
    __shared__ float soff[NH * NPT * 2];   // 64
    __shared__ float slog[NH * NPT];       // 32

    int bq = blockIdx.x;                 // 0..8191 = b*1024 + q
    int t  = threadIdx.x;                // 128 threads
    const float* qrow = query + (size_t)bq * CD;
    sq[t]       = qrow[t];
    sq[t + 128] = qrow[t + 128];
    __syncthreads();

    // 96 outputs total (64 offset + 32 attn); give first 96 threads one each
    if (t < 64) {
        float acc = boff[t];
        #pragma unroll 8
        for (int k = 0; k < CD; k++) acc += sq[k] * Woff[k * 64 + t];
        soff[t] = acc;
    } else if (t < 96) {
        int j = t - 64;
        float acc = battn[j];
        #pragma unroll 8
        for (int k = 0; k < CD; k++) acc += sq[k] * Wattn[k * 32 + j];
        slog[j] = acc;
    }
    __syncthreads();

    if (t < 32) {
        int h = t >> 2, p = t & 3;
        float l0 = slog[h * 4 + 0], l1 = slog[h * 4 + 1];
        float l2 = slog[h * 4 + 2], l3 = slog[h * 4 + 3];
        float m  = fmaxf(fmaxf(l0, l1), fmaxf(l2, l3));
        float e0 = __expf(l0 - m), e1 = __expf(l1 - m);
        float e2 = __expf(l2 - m), e3 = __expf(l3 - m);
        float inv = 1.0f / (e0 + e1 + e2 + e3);
        float ep  = (p == 0) ? e0 : (p == 1) ? e1 : (p == 2) ? e2 : e3;
        float w   = ep * inv;

        float refx = refp[bq * 2 + 0];
        float refy = refp[bq * 2 + 1];
        float ox = soff[(h * NPT + p) * 2 + 0];
        float oy = soff[(h * NPT + p) * 2 + 1];
        // grid_sample align_corners=False: pix = loc*Dim - 0.5, loc = ref + off/Dim
        float x = refx * (float)WWp + ox - 0.5f;
        float y = refy * (float)HH  + oy - 0.5f;
        g_samp[(size_t)bq * (NH * NPT) + t] = make_float4(x, y, w, 0.f);
    }
}

// ---------------- TF32 wmma GEMM: [M,256] @ [256,256] ------------------------
// MODE 0: A = memory, out -> g_value permuted layout [b][head][hw][d], bias = b_value
// MODE 1: A = g_S,    out -> row-major d_out,                         bias = b_out
#define BM 128
#define BN 64
#define BK 32
#define LDA 36
#define LDB 72
#define LDC 72

struct SmemGemm {
    union {
        struct { float a[BM * LDA]; float b[BK * LDB]; } ab;  // 27.6 KB
        float c[BM * LDC];                                    // 36.9 KB
    };
};

template <int MODE>
__global__ void __launch_bounds__(256)
k_gemm(const float* __restrict__ Ain, const float* __restrict__ Wt,
       const float* __restrict__ bias, float* __restrict__ out)
{
    __shared__ SmemGemm sm;
    const float* A = (MODE == 1) ? (const float*)g_S : Ain;

    int m0 = blockIdx.x * BM;
    int n0 = blockIdx.y * BN;
    int tid = threadIdx.x;          // 256
    int warpId = tid >> 5;
    int wr = warpId & 3;            // 4 row-groups of 32
    int wc = warpId >> 2;           // 2 col-groups of 32

    wmma::fragment<wmma::accumulator, 16, 16, 8, float> acc[2][2];
    #pragma unroll
    for (int i = 0; i < 2; i++)
        #pragma unroll
        for (int j = 0; j < 2; j++) wmma::fill_fragment(acc[i][j], 0.0f);

    for (int k0 = 0; k0 < CD; k0 += BK) {
        // A tile: 128x32  (1024 float4, 4 per thread)
        #pragma unroll
        for (int i = 0; i < 4; i++) {
            int f4 = tid * 4 + i;
            int r = f4 >> 3, c4 = f4 & 7;
            float4 v = *(const float4*)(A + (size_t)(m0 + r) * CD + k0 + c4 * 4);
            float* dst = &sm.ab.a[r * LDA + c4 * 4];
            dst[0] = wmma::__float_to_tf32(v.x);
            dst[1] = wmma::__float_to_tf32(v.y);
            dst[2] = wmma::__float_to_tf32(v.z);
            dst[3] = wmma::__float_to_tf32(v.w);
        }
        // B tile: 32x64 (512 float4, 2 per thread)
        #pragma unroll
        for (int i = 0; i < 2; i++) {
            int f4 = tid * 2 + i;
            int r = f4 >> 4, c4 = f4 & 15;
            float4 v = *(const float4*)(Wt + (size_t)(k0 + r) * CD + n0 + c4 * 4);
            float* dst = &sm.ab.b[r * LDB + c4 * 4];
            dst[0] = wmma::__float_to_tf32(v.x);
            dst[1] = wmma::__float_to_tf32(v.y);
            dst[2] = wmma::__float_to_tf32(v.z);
            dst[3] = wmma::__float_to_tf32(v.w);
        }
        __syncthreads();

        #pragma unroll
        for (int kk = 0; kk < BK; kk += 8) {
            wmma::fragment<wmma::matrix_a, 16, 16, 8, wmma::precision::tf32, wmma::row_major> af[2];
            wmma::fragment<wmma::matrix_b, 16, 16, 8, wmma::precision::tf32, wmma::row_major> bf[2];
            #pragma unroll
            for (int i = 0; i < 2; i++)
                wmma::load_matrix_sync(af[i], &sm.ab.a[(wr * 32 + i * 16) * LDA + kk], LDA);
            #pragma unroll
            for (int j = 0; j < 2; j++)
                wmma::load_matrix_sync(bf[j], &sm.ab.b[kk * LDB + wc * 32 + j * 16], LDB);
            #pragma unroll
            for (int i = 0; i < 2; i++)
                #pragma unroll
                for (int j = 0; j < 2; j++)
                    wmma::mma_sync(acc[i][j], af[i], bf[j], acc[i][j]);
        }
        __syncthreads();
    }

    // epilogue: fragments -> smem (reuses A/B region), then permuted global write
    #pragma unroll
    for (int i = 0; i < 2; i++)
        #pragma unroll
        for (int j = 0; j < 2; j++)
            wmma::store_matrix_sync(&sm.c[(wr * 32 + i * 16) * LDC + wc * 32 + j * 16],
                                    acc[i][j], LDC, wmma::mem_row_major);
    __syncthreads();

    #pragma unroll
    for (int it = 0; it < (BM * BN) / 256; it++) {
        int idx = it * 256 + tid;       // 0..8191
        int r = idx >> 6, cc = idx & 63;
        float v = sm.c[r * LDC + cc] + bias[n0 + cc];
        int m = m0 + r;
        if (MODE == 0) {
            int c = n0 + cc;
            int b = m >> 14;            // m / 16384
            int hw = m & 16383;
            int head = c >> 5, d = c & 31;
            g_value[((size_t)(b * NH + head) * HWSZ + hw) * HD + d] = v;
        } else {
            out[(size_t)m * CD + n0 + cc] = v;
        }
    }
}

// ---------------- kernel 3: bilinear gather + attention-weighted sum ---------
__global__ void __launch_bounds__(256) k_sample(int dummy)
{
    int gid  = blockIdx.x * 8 + (threadIdx.x >> 5);  // 0..65535 = (b*1024+q)*8 + h
    int lane = threadIdx.x & 31;                     // head-dim channel
    int h  = gid & 7;
    int bq = gid >> 3;
    int b  = bq >> 10;

    const float* vbase = g_value + (size_t)(b * NH + h) * HWSZ * HD;
    float acc = 0.0f;

    #pragma unroll
    for (int p = 0; p < NPT; p++) {
        float4 s = g_samp[(size_t)bq * (NH * NPT) + h * NPT + p];
        float x = s.x, y = s.y, w = s.z;
        float xf = floorf(x), yf = floorf(y);
        int ix = (int)xf, iy = (int)yf;
        float fx = x - xf, fy = y - yf;
        float w00 = w * (1.0f - fy) * (1.0f - fx);
        float w01 = w * (1.0f - fy) * fx;
        float w10 = w * fy * (1.0f - fx);
        float w11 = w * fy * fx;

        if ((unsigned)ix < (WWp - 1) && (unsigned)iy < (HH - 1)) {
            // fast path: all 4 corners interior -> 4 independent loads in flight
            const float* c00 = vbase + (size_t)(iy * WWp + ix) * HD + lane;
            float v00 = c00[0];
            float v01 = c00[HD];
            float v10 = c00[WWp * HD];
            float v11 = c00[WWp * HD + HD];
            acc += w00 * v00 + w01 * v01 + w10 * v10 + w11 * v11;
        } else {
            #pragma unroll
            for (int cy = 0; cy < 2; cy++) {
                int yy = iy + cy;
                if ((unsigned)yy >= HH) continue;
                #pragma unroll
                for (int cx = 0; cx < 2; cx++) {
                    int xx = ix + cx;
                    if ((unsigned)xx >= WWp) continue;
                    float cw = cy ? (cx ? w11 : w10) : (cx ? w01 : w00);
                    acc += cw * vbase[(size_t)(yy * WWp + xx) * HD + lane];
                }
            }
        }
    }
    g_S[(size_t)bq * CD + h * HD + lane] = acc;
}

// ---------------- launch -----------------------------------------------------
extern "C" void kernel_launch(void* const* d_in, const int* in_sizes, int n_in,
                              void* d_out, int out_size)
{
    const float* query  = (const float*)d_in[0];
    const float* memory = (const float*)d_in[1];
    const float* refp   = (const float*)d_in[2];
    const float* Wv     = (const float*)d_in[3];
    const float* bv     = (const float*)d_in[4];
    const float* Woff   = (const float*)d_in[5];
    const float* boff   = (const float*)d_in[6];
    const float* Wattn  = (const float*)d_in[7];
    const float* battn  = (const float*)d_in[8];
    const float* Wout   = (const float*)d_in[9];
    const float* bout   = (const float*)d_in[10];
    float* out = (float*)d_out;

    // 1) offsets / attn weights / sample coordinates
    k_offsets<<<NB * LQ, 128>>>(query, refp, Woff, boff, Wattn, battn);

    // 2) value projection GEMM -> permuted value layout
    k_gemm<0><<<dim3((NB * HWSZ) / BM, CD / BN), 256>>>(memory, Wv, bv, nullptr);

    // 3) bilinear sampling + attention-weighted reduce
    k_sample<<<(NB * LQ * NH) / 8, 256>>>(0);

    // 4) output projection GEMM (reads g_S internally)
    k_gemm<1><<<dim3((NB * LQ) / BM, CD / BN), 256>>>(nullptr, Wout, bout, out);
}

// round 8
// speedup vs baseline: 1.0727x; 1.0727x over previous
#include <cstdint>
#include <cuda_runtime.h>
#include <cuda_bf16.h>
#include <mma.h>

using namespace nvcuda;

// Problem constants (fixed shapes per reference setup_inputs)
#define NB   8      // batch
#define LQ   1024   // queries
#define CD   256    // d_model
#define NH   8      // heads
#define NPT  4      // points
#define HD   32     // head dim
#define HH   128
#define WWp  128
#define HWSZ (HH * WWp)

// ---------------- scratch (device globals; no allocations allowed) ----------
__device__ float  g_value[(size_t)NB * NH * HWSZ * HD];   // [b][h][y*W+x][d]  134 MB
__device__ float4 g_samp[(size_t)NB * LQ * NH * NPT];     // (x_pix, y_pix, attn_w, _)
__device__ float  g_S[(size_t)NB * LQ * CD];              // sampled [b][q][h*32+d]

// =====================================================================
// kernel 1: offsets + attn weights + sample coords, 32 queries per block
// =====================================================================
#define QB 32
__global__ void __launch_bounds__(256) k_offsets(
    const float* __restrict__ query,
    const float* __restrict__ refp,
    const float* __restrict__ Woff, const float* __restrict__ boff,
    const float* __restrict__ Wattn, const float* __restrict__ battn)
{
    __shared__ float sq[QB][CD + 4];   // 33.3 KB
    __shared__ float sp[QB][96 + 2];   // 12.5 KB

    int q0  = blockIdx.x * QB;
    int tid = threadIdx.x;

    // load 32 query rows (2048 float4, 8 per thread)
    #pragma unroll
    for (int i = 0; i < 8; i++) {
        int id = i * 256 + tid;
        int q = id >> 6, c4 = id & 63;
        float4 v = *(const float4*)(query + (size_t)(q0 + q) * CD + c4 * 4);
        *(float4*)&sq[q][c4 * 4] = v;
    }
    __syncthreads();

    // GEMV: 32 q x 96 outputs. lane j0 = tid&31 handles cols {j0, j0+32(off), j0(attn)},
    // warp qg = tid>>5 handles queries {qg, qg+8, qg+16, qg+24}.
    {
        int j0 = tid & 31;
        int qg = tid >> 5;
        float a0[4], a1[4], a2[4];
        #pragma unroll
        for (int m = 0; m < 4; m++) {
            a0[m] = boff[j0];
            a1[m] = boff[j0 + 32];
            a2[m] = battn[j0];
        }
        #pragma unroll 8
        for (int k = 0; k < CD; k++) {
            float w0 = Woff[k * 64 + j0];
            float w1 = Woff[k * 64 + 32 + j0];
            float w2 = Wattn[k * 32 + j0];
            #pragma unroll
            for (int m = 0; m < 4; m++) {
                float s = sq[qg + 8 * m][k];   // broadcast within warp
                a0[m] += w0 * s;
                a1[m] += w1 * s;
                a2[m] += w2 * s;
            }
        }
        #pragma unroll
        for (int m = 0; m < 4; m++) {
            sp[qg + 8 * m][j0]      = a0[m];
            sp[qg + 8 * m][32 + j0] = a1[m];
            sp[qg + 8 * m][64 + j0] = a2[m];
        }
    }
    __syncthreads();

    // finalize: softmax over points + pixel coords; 1024 items, 4 per thread
    #pragma unroll
    for (int i = 0; i < 4; i++) {
        int item = i * 256 + tid;       // q_local*32 + h*4 + p
        int q = item >> 5, t32 = item & 31;
        int h = t32 >> 2, p = t32 & 3;

        float l0 = sp[q][64 + h * 4 + 0], l1 = sp[q][64 + h * 4 + 1];
        float l2 = sp[q][64 + h * 4 + 2], l3 = sp[q][64 + h * 4 + 3];
        float m  = fmaxf(fmaxf(l0, l1), fmaxf(l2, l3));
        float e0 = __expf(l0 - m), e1 = __expf(l1 - m);
        float e2 = __expf(l2 - m), e3 = __expf(l3 - m);
        float inv = 1.0f / (e0 + e1 + e2 + e3);
        float ep  = (p == 0) ? e0 : (p == 1) ? e1 : (p == 2) ? e2 : e3;
        float w   = ep * inv;

        int bq = q0 + q;
        float refx = refp[bq * 2 + 0];
        float refy = refp[bq * 2 + 1];
        float ox = sp[q][(h * NPT + p) * 2 + 0];
        float oy = sp[q][(h * NPT + p) * 2 + 1];
        // grid_sample align_corners=False: pix = (ref + off/Dim)*Dim - 0.5
        float x = refx * (float)WWp + ox - 0.5f;
        float y = refy * (float)HH  + oy - 0.5f;
        g_samp[(size_t)bq * (NH * NPT) + t32] = make_float4(x, y, w, 0.f);
    }
}

// =====================================================================
// pipelined TF32 wmma GEMM: [M,256] @ [256,256]
// MODE 0: A = memory, out -> g_value permuted [b][head][hw][d]
// MODE 1: A = g_S,    out -> row-major d_out
// =====================================================================
#define BM 128
#define BN 64
#define BK 16
#define LDA 20
#define LDB 68
#define LDC 68

struct __align__(16) SmemGemm {
    union {
        struct { float a[2][BM * LDA]; float b[2][BK * LDB]; } ab;  // 29.2 KB
        float c[BM * LDC];                                          // 34.8 KB
    };
};

__device__ __forceinline__ void cpasync16(void* smem_dst, const void* gmem_src) {
    unsigned int s = (unsigned int)__cvta_generic_to_shared(smem_dst);
    asm volatile("cp.async.cg.shared.global [%0], [%1], 16;" :: "r"(s), "l"(gmem_src));
}
__device__ __forceinline__ void cpasync_commit() {
    asm volatile("cp.async.commit_group;");
}
__device__ __forceinline__ void cpasync_wait0() {
    asm volatile("cp.async.wait_group 0;");
}

template <int MODE>
__global__ void __launch_bounds__(256)
k_gemm(const float* __restrict__ Ain, const float* __restrict__ Wt,
       const float* __restrict__ bias, float* __restrict__ out)
{
    __shared__ SmemGemm sm;
    const float* A = (MODE == 1) ? (const float*)g_S : Ain;

    int n0 = blockIdx.x * BN;       // x = N-block so A-sharing blocks are adjacent
    int m0 = blockIdx.y * BM;
    int tid = threadIdx.x;          // 256
    int warpId = tid >> 5;
    int wr = warpId >> 1;           // 4 row-groups (32 rows each)
    int wc = warpId & 1;            // 2 col-groups (32 cols each)

    wmma::fragment<wmma::accumulator, 16, 16, 8, float> acc[2][2];
    #pragma unroll
    for (int i = 0; i < 2; i++)
        #pragma unroll
        for (int j = 0; j < 2; j++) wmma::fill_fragment(acc[i][j], 0.0f);

    // tile loaders: A 128x16 (512 f4, 2/thread), B 16x64 (256 f4, 1/thread)
    auto load_tiles = [&](int buf, int k0) {
        #pragma unroll
        for (int i = 0; i < 2; i++) {
            int f4 = tid + i * 256;
            int r = f4 >> 2, c4 = f4 & 3;
            cpasync16(&sm.ab.a[buf][r * LDA + c4 * 4],
                      A + (size_t)(m0 + r) * CD + k0 + c4 * 4);
        }
        {
            int r = tid >> 4, c4 = tid & 15;   // 16 rows x 16 float4 = full 16x64 tile
            cpasync16(&sm.ab.b[buf][r * LDB + c4 * 4],
                      Wt + (size_t)(k0 + r) * CD + n0 + c4 * 4);
        }
        cpasync_commit();
    };

    load_tiles(0, 0);

    const int NIT = CD / BK;        // 16
    for (int it = 0; it < NIT; ++it) {
        cpasync_wait0();
        __syncthreads();
        if (it + 1 < NIT) load_tiles((it + 1) & 1, (it + 1) * BK);

        int buf = it & 1;
        #pragma unroll
        for (int kk = 0; kk < BK; kk += 8) {
            wmma::fragment<wmma::matrix_a, 16, 16, 8, wmma::precision::tf32, wmma::row_major> af[2];
            wmma::fragment<wmma::matrix_b, 16, 16, 8, wmma::precision::tf32, wmma::row_major> bf[2];
            #pragma unroll
            for (int i = 0; i < 2; i++) {
                wmma::load_matrix_sync(af[i], &sm.ab.a[buf][(wr * 32 + i * 16) * LDA + kk], LDA);
                #pragma unroll
                for (int e = 0; e < af[i].num_elements; e++)
                    af[i].x[e] = wmma::__float_to_tf32(af[i].x[e]);
            }
            #pragma unroll
            for (int j = 0; j < 2; j++) {
                wmma::load_matrix_sync(bf[j], &sm.ab.b[buf][kk * LDB + wc * 32 + j * 16], LDB);
                #pragma unroll
                for (int e = 0; e < bf[j].num_elements; e++)
                    bf[j].x[e] = wmma::__float_to_tf32(bf[j].x[e]);
            }
            #pragma unroll
            for (int i = 0; i < 2; i++)
                #pragma unroll
                for (int j = 0; j < 2; j++)
                    wmma::mma_sync(acc[i][j], af[i], bf[j], acc[i][j]);
        }
        __syncthreads();
    }

    // epilogue: fragments -> smem (union reuse), then vectorized global write
    #pragma unroll
    for (int i = 0; i < 2; i++)
        #pragma unroll
        for (int j = 0; j < 2; j++)
            wmma::store_matrix_sync(&sm.c[(wr * 32 + i * 16) * LDC + wc * 32 + j * 16],
                                    acc[i][j], LDC, wmma::mem_row_major);
    __syncthreads();

    #pragma unroll
    for (int i = 0; i < 8; i++) {
        int id = i * 256 + tid;         // 2048 float4
        int r = id >> 4, c4 = id & 15;
        float4 v = *(float4*)&sm.c[r * LDC + c4 * 4];
        int col = n0 + c4 * 4;
        v.x += bias[col]; v.y += bias[col + 1]; v.z += bias[col + 2]; v.w += bias[col + 3];
        int m = m0 + r;
        if (MODE == 0) {
            int b = m >> 14;            // m / 16384
            int hw = m & 16383;
            int head = col >> 5, d = col & 31;   // 4 consecutive d within one head
            *(float4*)&g_value[((size_t)(b * NH + head) * HWSZ + hw) * HD + d] = v;
        } else {
            *(float4*)&out[(size_t)m * CD + col] = v;
        }
    }
}

// =====================================================================
// kernel 3: bilinear gather + attention-weighted sum
// =====================================================================
__global__ void __launch_bounds__(256) k_sample(int dummy)
{
    int gid  = blockIdx.x * 8 + (threadIdx.x >> 5);  // 0..65535 = (b*1024+q)*8 + h
    int lane = threadIdx.x & 31;                     // head-dim channel
    int h  = gid & 7;
    int bq = gid >> 3;
    int b  = bq >> 10;

    const float* vbase = g_value + (size_t)(b * NH + h) * HWSZ * HD;
    float acc = 0.0f;

    #pragma unroll
    for (int p = 0; p < NPT; p++) {
        float4 s = g_samp[(size_t)bq * (NH * NPT) + h * NPT + p];
        float x = s.x, y = s.y, w = s.z;
        float xf = floorf(x), yf = floorf(y);
        int ix = (int)xf, iy = (int)yf;
        float fx = x - xf, fy = y - yf;
        float w00 = w * (1.0f - fy) * (1.0f - fx);
        float w01 = w * (1.0f - fy) * fx;
        float w10 = w * fy * (1.0f - fx);
        float w11 = w * fy * fx;

        if ((unsigned)ix < (WWp - 1) && (unsigned)iy < (HH - 1)) {
            const float* c00 = vbase + (size_t)(iy * WWp + ix) * HD + lane;
            float v00 = c00[0];
            float v01 = c00[HD];
            float v10 = c00[WWp * HD];
            float v11 = c00[WWp * HD + HD];
            acc += w00 * v00 + w01 * v01 + w10 * v10 + w11 * v11;
        } else {
            #pragma unroll
            for (int cy = 0; cy < 2; cy++) {
                int yy = iy + cy;
                if ((unsigned)yy >= HH) continue;
                #pragma unroll
                for (int cx = 0; cx < 2; cx++) {
                    int xx = ix + cx;
                    if ((unsigned)xx >= WWp) continue;
                    float cw = cy ? (cx ? w11 : w10) : (cx ? w01 : w00);
                    acc += cw * vbase[(size_t)(yy * WWp + xx) * HD + lane];
                }
            }
        }
    }
    g_S[(size_t)bq * CD + h * HD + lane] = acc;
}

// ---------------- launch -----------------------------------------------------
extern "C" void kernel_launch(void* const* d_in, const int* in_sizes, int n_in,
                              void* d_out, int out_size)
{
    const float* query  = (const float*)d_in[0];
    const float* memory = (const float*)d_in[1];
    const float* refp   = (const float*)d_in[2];
    const float* Wv     = (const float*)d_in[3];
    const float* bv     = (const float*)d_in[4];
    const float* Woff   = (const float*)d_in[5];
    const float* boff   = (const float*)d_in[6];
    const float* Wattn  = (const float*)d_in[7];
    const float* battn  = (const float*)d_in[8];
    const float* Wout   = (const float*)d_in[9];
    const float* bout   = (const float*)d_in[10];
    float* out = (float*)d_out;

    // 1) offsets / attn weights / sample coordinates
    k_offsets<<<(NB * LQ) / QB, 256>>>(query, refp, Woff, boff, Wattn, battn);

    // 2) value projection GEMM -> permuted value layout
    k_gemm<0><<<dim3(CD / BN, (NB * HWSZ) / BM), 256>>>(memory, Wv, bv, nullptr);

    // 3) bilinear sampling + attention-weighted reduce
    k_sample<<<(NB * LQ * NH) / 8, 256>>>(0);

    // 4) output projection GEMM (reads g_S internally)
    k_gemm<1><<<dim3(CD / BN, (NB * LQ) / BM), 256>>>(nullptr, Wout, bout, out);
}

// round 9
// speedup vs baseline: 1.0761x; 1.0032x over previous
#include <cstdint>
#include <cuda_runtime.h>
#include <cuda_bf16.h>
#include <mma.h>

using namespace nvcuda;

// Problem constants (fixed shapes per reference setup_inputs)
#define NB   8      // batch
#define LQ   1024   // queries
#define CD   256    // d_model
#define NH   8      // heads
#define NPT  4      // points
#define HD   32     // head dim
#define HH   128
#define WWp  128
#define HWSZ (HH * WWp)

// ---------------- scratch (device globals; no allocations allowed) ----------
__device__ float  g_value[(size_t)NB * NH * HWSZ * HD];   // [b][h][y*W+x][d]  134 MB
__device__ float4 g_samp[(size_t)NB * LQ * NH * NPT];     // (x_pix, y_pix, attn_w, _)
__device__ float  g_S[(size_t)NB * LQ * CD];              // sampled [b][q][h*32+d]

// =====================================================================
// kernel 1: offsets + attn weights + sample coords, 32 queries per block
// =====================================================================
#define QB 32
__global__ void __launch_bounds__(256) k_offsets(
    const float* __restrict__ query,
    const float* __restrict__ refp,
    const float* __restrict__ Woff, const float* __restrict__ boff,
    const float* __restrict__ Wattn, const float* __restrict__ battn)
{
    __shared__ float sq[QB][CD + 4];   // 33.3 KB
    __shared__ float sp[QB][96 + 2];   // 12.5 KB

    int q0  = blockIdx.x * QB;
    int tid = threadIdx.x;

    // load 32 query rows (2048 float4, 8 per thread)
    #pragma unroll
    for (int i = 0; i < 8; i++) {
        int id = i * 256 + tid;
        int q = id >> 6, c4 = id & 63;
        float4 v = *(const float4*)(query + (size_t)(q0 + q) * CD + c4 * 4);
        *(float4*)&sq[q][c4 * 4] = v;
    }
    __syncthreads();

    // GEMV: 32 q x 96 outputs. lane j0 = tid&31 handles cols {j0, j0+32(off), j0(attn)},
    // warp qg = tid>>5 handles queries {qg, qg+8, qg+16, qg+24}.
    {
        int j0 = tid & 31;
        int qg = tid >> 5;
        float a0[4], a1[4], a2[4];
        #pragma unroll
        for (int m = 0; m < 4; m++) {
            a0[m] = boff[j0];
            a1[m] = boff[j0 + 32];
            a2[m] = battn[j0];
        }
        #pragma unroll 8
        for (int k = 0; k < CD; k++) {
            float w0 = Woff[k * 64 + j0];
            float w1 = Woff[k * 64 + 32 + j0];
            float w2 = Wattn[k * 32 + j0];
            #pragma unroll
            for (int m = 0; m < 4; m++) {
                float s = sq[qg + 8 * m][k];   // broadcast within warp
                a0[m] += w0 * s;
                a1[m] += w1 * s;
                a2[m] += w2 * s;
            }
        }
        #pragma unroll
        for (int m = 0; m < 4; m++) {
            sp[qg + 8 * m][j0]      = a0[m];
            sp[qg + 8 * m][32 + j0] = a1[m];
            sp[qg + 8 * m][64 + j0] = a2[m];
        }
    }
    __syncthreads();

    // finalize: softmax over points + pixel coords; 1024 items, 4 per thread
    #pragma unroll
    for (int i = 0; i < 4; i++) {
        int item = i * 256 + tid;       // q_local*32 + h*4 + p
        int q = item >> 5, t32 = item & 31;
        int h = t32 >> 2, p = t32 & 3;

        float l0 = sp[q][64 + h * 4 + 0], l1 = sp[q][64 + h * 4 + 1];
        float l2 = sp[q][64 + h * 4 + 2], l3 = sp[q][64 + h * 4 + 3];
        float m  = fmaxf(fmaxf(l0, l1), fmaxf(l2, l3));
        float e0 = __expf(l0 - m), e1 = __expf(l1 - m);
        float e2 = __expf(l2 - m), e3 = __expf(l3 - m);
        float inv = 1.0f / (e0 + e1 + e2 + e3);
        float ep  = (p == 0) ? e0 : (p == 1) ? e1 : (p == 2) ? e2 : e3;
        float w   = ep * inv;

        int bq = q0 + q;
        float refx = refp[bq * 2 + 0];
        float refy = refp[bq * 2 + 1];
        float ox = sp[q][(h * NPT + p) * 2 + 0];
        float oy = sp[q][(h * NPT + p) * 2 + 1];
        // grid_sample align_corners=False: pix = (ref + off/Dim)*Dim - 0.5
        float x = refx * (float)WWp + ox - 0.5f;
        float y = refy * (float)HH  + oy - 0.5f;
        g_samp[(size_t)bq * (NH * NPT) + t32] = make_float4(x, y, w, 0.f);
    }
}

// =====================================================================
// 3-stage pipelined TF32 wmma GEMM: [M,256] @ [256,256]
// MODE 0: A = memory, out -> g_value permuted [b][head][hw][d]
// MODE 1: A = g_S,    out -> row-major d_out
// =====================================================================
#define BM 128
#define BN 64
#define BK 16
#define NSTG 3
#define LDA 20
#define LDB 68
#define LDC 68

struct __align__(16) SmemGemm {
    union {
        struct { float a[NSTG][BM * LDA]; float b[NSTG][BK * LDB]; } ab;  // 43.8 KB
        float c[BM * LDC];                                                // 34.8 KB
    };
};

__device__ __forceinline__ void cpasync16(void* smem_dst, const void* gmem_src) {
    unsigned int s = (unsigned int)__cvta_generic_to_shared(smem_dst);
    asm volatile("cp.async.cg.shared.global [%0], [%1], 16;" :: "r"(s), "l"(gmem_src));
}
__device__ __forceinline__ void cpasync_commit() {
    asm volatile("cp.async.commit_group;");
}
__device__ __forceinline__ void cpasync_wait1() {
    asm volatile("cp.async.wait_group 1;");
}

template <int MODE>
__global__ void __launch_bounds__(256)
k_gemm(const float* __restrict__ Ain, const float* __restrict__ Wt,
       const float* __restrict__ bias, float* __restrict__ out)
{
    __shared__ SmemGemm sm;
    const float* A = (MODE == 1) ? (const float*)g_S : Ain;

    int n0 = blockIdx.x * BN;       // x = N-block so A-sharing blocks are adjacent
    int m0 = blockIdx.y * BM;
    int tid = threadIdx.x;          // 256
    int warpId = tid >> 5;
    int wr = warpId >> 1;           // 4 row-groups (32 rows each)
    int wc = warpId & 1;            // 2 col-groups (32 cols each)

    wmma::fragment<wmma::accumulator, 16, 16, 8, float> acc[2][2];
    #pragma unroll
    for (int i = 0; i < 2; i++)
        #pragma unroll
        for (int j = 0; j < 2; j++) wmma::fill_fragment(acc[i][j], 0.0f);

    // tile loaders: A 128x16 (512 f4, 2/thread), B 16x64 (256 f4, 1/thread)
    auto load_tiles = [&](int buf, int k0) {
        #pragma unroll
        for (int i = 0; i < 2; i++) {
            int f4 = tid + i * 256;
            int r = f4 >> 2, c4 = f4 & 3;
            cpasync16(&sm.ab.a[buf][r * LDA + c4 * 4],
                      A + (size_t)(m0 + r) * CD + k0 + c4 * 4);
        }
        {
            int r = tid >> 4, c4 = tid & 15;   // 16 rows x 16 float4 = full 16x64 tile
            cpasync16(&sm.ab.b[buf][r * LDB + c4 * 4],
                      Wt + (size_t)(k0 + r) * CD + n0 + c4 * 4);
        }
        cpasync_commit();
    };

    // prologue: stages 0 and 1 in flight
    load_tiles(0, 0);
    load_tiles(1, BK);

    const int NIT = CD / BK;        // 16
    for (int it = 0; it < NIT; ++it) {
        cpasync_wait1();            // stage `it` landed (2 groups pending -> 1)
        __syncthreads();
        // issue stage it+2 into buffer (it+2)%3 == (it-1)%3 (freed at last barrier);
        // empty commit in tail keeps the pending-group count invariant
        if (it + 2 < NIT) load_tiles((it + 2) % NSTG, (it + 2) * BK);
        else              cpasync_commit();

        int buf = it % NSTG;
        #pragma unroll
        for (int kk = 0; kk < BK; kk += 8) {
            wmma::fragment<wmma::matrix_a, 16, 16, 8, wmma::precision::tf32, wmma::row_major> af[2];
            wmma::fragment<wmma::matrix_b, 16, 16, 8, wmma::precision::tf32, wmma::row_major> bf[2];
            #pragma unroll
            for (int i = 0; i < 2; i++) {
                wmma::load_matrix_sync(af[i], &sm.ab.a[buf][(wr * 32 + i * 16) * LDA + kk], LDA);
                #pragma unroll
                for (int e = 0; e < af[i].num_elements; e++)
                    af[i].x[e] = wmma::__float_to_tf32(af[i].x[e]);
            }
            #pragma unroll
            for (int j = 0; j < 2; j++) {
                wmma::load_matrix_sync(bf[j], &sm.ab.b[buf][kk * LDB + wc * 32 + j * 16], LDB);
                #pragma unroll
                for (int e = 0; e < bf[j].num_elements; e++)
                    bf[j].x[e] = wmma::__float_to_tf32(bf[j].x[e]);
            }
            #pragma unroll
            for (int i = 0; i < 2; i++)
                #pragma unroll
                for (int j = 0; j < 2; j++)
                    wmma::mma_sync(acc[i][j], af[i], bf[j], acc[i][j]);
        }
        __syncthreads();
    }

    // epilogue: fragments -> smem (union reuse), then vectorized global write
    #pragma unroll
    for (int i = 0; i < 2; i++)
        #pragma unroll
        for (int j = 0; j < 2; j++)
            wmma::store_matrix_sync(&sm.c[(wr * 32 + i * 16) * LDC + wc * 32 + j * 16],
                                    acc[i][j], LDC, wmma::mem_row_major);
    __syncthreads();

    #pragma unroll
    for (int i = 0; i < 8; i++) {
        int id = i * 256 + tid;         // 2048 float4
        int r = id >> 4, c4 = id & 15;
        float4 v = *(float4*)&sm.c[r * LDC + c4 * 4];
        int col = n0 + c4 * 4;
        v.x += bias[col]; v.y += bias[col + 1]; v.z += bias[col + 2]; v.w += bias[col + 3];
        int m = m0 + r;
        if (MODE == 0) {
            int b = m >> 14;            // m / 16384
            int hw = m & 16383;
            int head = col >> 5, d = col & 31;   // 4 consecutive d within one head
            *(float4*)&g_value[((size_t)(b * NH + head) * HWSZ + hw) * HD + d] = v;
        } else {
            *(float4*)&out[(size_t)m * CD + col] = v;
        }
    }
}

// =====================================================================
// kernel 3: bilinear gather + attention-weighted sum
// =====================================================================
__global__ void __launch_bounds__(256) k_sample(int dummy)
{
    int gid  = blockIdx.x * 8 + (threadIdx.x >> 5);  // 0..65535 = (b*1024+q)*8 + h
    int lane = threadIdx.x & 31;                     // head-dim channel
    int h  = gid & 7;
    int bq = gid >> 3;
    int b  = bq >> 10;

    const float* vbase = g_value + (size_t)(b * NH + h) * HWSZ * HD;
    float acc = 0.0f;

    #pragma unroll
    for (int p = 0; p < NPT; p++) {
        float4 s = g_samp[(size_t)bq * (NH * NPT) + h * NPT + p];
        float x = s.x, y = s.y, w = s.z;
        float xf = floorf(x), yf = floorf(y);
        int ix = (int)xf, iy = (int)yf;
        float fx = x - xf, fy = y - yf;
        float w00 = w * (1.0f - fy) * (1.0f - fx);
        float w01 = w * (1.0f - fy) * fx;
        float w10 = w * fy * (1.0f - fx);
        float w11 = w * fy * fx;

        if ((unsigned)ix < (WWp - 1) && (unsigned)iy < (HH - 1)) {
            const float* c00 = vbase + (size_t)(iy * WWp + ix) * HD + lane;
            float v00 = c00[0];
            float v01 = c00[HD];
            float v10 = c00[WWp * HD];
            float v11 = c00[WWp * HD + HD];
            acc += w00 * v00 + w01 * v01 + w10 * v10 + w11 * v11;
        } else {
            #pragma unroll
            for (int cy = 0; cy < 2; cy++) {
                int yy = iy + cy;
                if ((unsigned)yy >= HH) continue;
                #pragma unroll
                for (int cx = 0; cx < 2; cx++) {
                    int xx = ix + cx;
                    if ((unsigned)xx >= WWp) continue;
                    float cw = cy ? (cx ? w11 : w10) : (cx ? w01 : w00);
                    acc += cw * vbase[(size_t)(yy * WWp + xx) * HD + lane];
                }
            }
        }
    }
    g_S[(size_t)bq * CD + h * HD + lane] = acc;
}

// ---------------- launch -----------------------------------------------------
extern "C" void kernel_launch(void* const* d_in, const int* in_sizes, int n_in,
                              void* d_out, int out_size)
{
    const float* query  = (const float*)d_in[0];
    const float* memory = (const float*)d_in[1];
    const float* refp   = (const float*)d_in[2];
    const float* Wv     = (const float*)d_in[3];
    const float* bv     = (const float*)d_in[4];
    const float* Woff   = (const float*)d_in[5];
    const float* boff   = (const float*)d_in[6];
    const float* Wattn  = (const float*)d_in[7];
    const float* battn  = (const float*)d_in[8];
    const float* Wout   = (const float*)d_in[9];
    const float* bout   = (const float*)d_in[10];
    float* out = (float*)d_out;

    // 1) offsets / attn weights / sample coordinates
    k_offsets<<<(NB * LQ) / QB, 256>>>(query, refp, Woff, boff, Wattn, battn);

    // 2) value projection GEMM -> permuted value layout
    k_gemm<0><<<dim3(CD / BN, (NB * HWSZ) / BM), 256>>>(memory, Wv, bv, nullptr);

    // 3) bilinear sampling + attention-weighted reduce
    k_sample<<<(NB * LQ * NH) / 8, 256>>>(0);

    // 4) output projection GEMM (reads g_S internally)
    k_gemm<1><<<dim3(CD / BN, (NB * LQ) / BM), 256>>>(nullptr, Wout, bout, out);
}

// round 11
// speedup vs baseline: 2.5730x; 2.3910x over previous
#include <cstdint>
#include <cuda_runtime.h>
#include <mma.h>

using namespace nvcuda;

// Problem constants (fixed shapes per reference setup_inputs)
#define NB   8
#define LQ   1024
#define CD   256
#define NH   8
#define NPT  4
#define HD   32
#define HH   128
#define WWp  128
#define HWSZ (HH * WWp)

// ---------------- scratch (device globals; no allocations allowed) ----------
__device__ float4 g_samp[(size_t)NB * LQ * NH * NPT];     // (x_pix, y_pix, attn_w, _)
__device__ float  g_U[(size_t)NH * NB * LQ * CD];         // gathered memory rows, head-major (67 MB)
__device__ float  g_sw[(size_t)NB * LQ * NH];             // sum of effective bilinear*attn weights
__device__ float  g_S[(size_t)NB * LQ * CD];              // sampled values [bq][h*32+d]

// =====================================================================
// kernel 1: offsets + attn weights + sample coords, 32 queries per block
// =====================================================================
#define QB 32
__global__ void __launch_bounds__(256) k_offsets(
    const float* __restrict__ query,
    const float* __restrict__ refp,
    const float* __restrict__ Woff, const float* __restrict__ boff,
    const float* __restrict__ Wattn, const float* __restrict__ battn)
{
    __shared__ float sq[QB][CD + 4];
    __shared__ float sp[QB][96 + 2];

    int q0  = blockIdx.x * QB;
    int tid = threadIdx.x;

    #pragma unroll
    for (int i = 0; i < 8; i++) {
        int id = i * 256 + tid;
        int q = id >> 6, c4 = id & 63;
        float4 v = *(const float4*)(query + (size_t)(q0 + q) * CD + c4 * 4);
        *(float4*)&sq[q][c4 * 4] = v;
    }
    __syncthreads();

    {
        int j0 = tid & 31;
        int qg = tid >> 5;
        float a0[4], a1[4], a2[4];
        #pragma unroll
        for (int m = 0; m < 4; m++) {
            a0[m] = boff[j0];
            a1[m] = boff[j0 + 32];
            a2[m] = battn[j0];
        }
        #pragma unroll 8
        for (int k = 0; k < CD; k++) {
            float w0 = Woff[k * 64 + j0];
            float w1 = Woff[k * 64 + 32 + j0];
            float w2 = Wattn[k * 32 + j0];
            #pragma unroll
            for (int m = 0; m < 4; m++) {
                float s = sq[qg + 8 * m][k];
                a0[m] += w0 * s;
                a1[m] += w1 * s;
                a2[m] += w2 * s;
            }
        }
        #pragma unroll
        for (int m = 0; m < 4; m++) {
            sp[qg + 8 * m][j0]      = a0[m];
            sp[qg + 8 * m][32 + j0] = a1[m];
            sp[qg + 8 * m][64 + j0] = a2[m];
        }
    }
    __syncthreads();

    #pragma unroll
    for (int i = 0; i < 4; i++) {
        int item = i * 256 + tid;
        int q = item >> 5, t32 = item & 31;
        int h = t32 >> 2, p = t32 & 3;

        float l0 = sp[q][64 + h * 4 + 0], l1 = sp[q][64 + h * 4 + 1];
        float l2 = sp[q][64 + h * 4 + 2], l3 = sp[q][64 + h * 4 + 3];
        float m  = fmaxf(fmaxf(l0, l1), fmaxf(l2, l3));
        float e0 = __expf(l0 - m), e1 = __expf(l1 - m);
        float e2 = __expf(l2 - m), e3 = __expf(l3 - m);
        float inv = 1.0f / (e0 + e1 + e2 + e3);
        float ep  = (p == 0) ? e0 : (p == 1) ? e1 : (p == 2) ? e2 : e3;
        float w   = ep * inv;

        int bq = q0 + q;
        float refx = refp[bq * 2 + 0];
        float refy = refp[bq * 2 + 1];
        float ox = sp[q][(h * NPT + p) * 2 + 0];
        float oy = sp[q][(h * NPT + p) * 2 + 1];
        // grid_sample align_corners=False: pix = (ref + off/Dim)*Dim - 0.5
        float x = refx * (float)WWp + ox - 0.5f;
        float y = refy * (float)HH  + oy - 0.5f;
        g_samp[(size_t)bq * (NH * NPT) + t32] = make_float4(x, y, w, 0.f);
    }
}

// =====================================================================
// kernel 2: weighted gather of RAW memory rows (sampling commuted with
// value projection). Block = query (bq); warp h = head h; lane owns 8 cols.
// U[h][bq][:] = sum over 16 corners of (attn*bilinear) * memory[b, pixel, :]
// g_sw[bq][h]  = sum of in-bounds effective weights (for bias term)
// =====================================================================
__global__ void __launch_bounds__(256) k_gather(const float* __restrict__ memory)
{
    int bq   = blockIdx.x;
    int h    = threadIdx.x >> 5;
    int lane = threadIdx.x & 31;
    int b    = bq >> 10;

    const float* mb = memory + (size_t)b * HWSZ * CD + lane * 8;

    float acc[8] = {0.f, 0.f, 0.f, 0.f, 0.f, 0.f, 0.f, 0.f};
    float s = 0.f;

    #pragma unroll
    for (int p = 0; p < NPT; p++) {
        float4 sm = g_samp[(size_t)bq * (NH * NPT) + h * NPT + p];
        float x = sm.x, y = sm.y, w = sm.z;
        float xf = floorf(x), yf = floorf(y);
        int ix = (int)xf, iy = (int)yf;
        float fx = x - xf, fy = y - yf;
        float w00 = w * (1.0f - fy) * (1.0f - fx);
        float w01 = w * (1.0f - fy) * fx;
        float w10 = w * fy * (1.0f - fx);
        float w11 = w * fy * fx;

        if ((unsigned)ix < (WWp - 1) && (unsigned)iy < (HH - 1)) {
            // fast path: 4 interior corners -> 8 independent 16B loads in flight
            const float* c00 = mb + (size_t)(iy * WWp + ix) * CD;
            float4 a0 = *(const float4*)(c00);
            float4 a1 = *(const float4*)(c00 + 4);
            float4 b0 = *(const float4*)(c00 + CD);
            float4 b1 = *(const float4*)(c00 + CD + 4);
            float4 c0 = *(const float4*)(c00 + WWp * CD);
            float4 c1 = *(const float4*)(c00 + WWp * CD + 4);
            float4 d0 = *(const float4*)(c00 + WWp * CD + CD);
            float4 d1 = *(const float4*)(c00 + WWp * CD + CD + 4);
            acc[0] += w00 * a0.x + w01 * b0.x + w10 * c0.x + w11 * d0.x;
            acc[1] += w00 * a0.y + w01 * b0.y + w10 * c0.y + w11 * d0.y;
            acc[2] += w00 * a0.z + w01 * b0.z + w10 * c0.z + w11 * d0.z;
            acc[3] += w00 * a0.w + w01 * b0.w + w10 * c0.w + w11 * d0.w;
            acc[4] += w00 * a1.x + w01 * b1.x + w10 * c1.x + w11 * d1.x;
            acc[5] += w00 * a1.y + w01 * b1.y + w10 * c1.y + w11 * d1.y;
            acc[6] += w00 * a1.z + w01 * b1.z + w10 * c1.z + w11 * d1.z;
            acc[7] += w00 * a1.w + w01 * b1.w + w10 * c1.w + w11 * d1.w;
            s += w;
        } else {
            #pragma unroll
            for (int cy = 0; cy < 2; cy++) {
                int yy = iy + cy;
                if ((unsigned)yy >= HH) continue;
                #pragma unroll
                for (int cx = 0; cx < 2; cx++) {
                    int xx = ix + cx;
                    if ((unsigned)xx >= WWp) continue;
                    float cw = cy ? (cx ? w11 : w10) : (cx ? w01 : w00);
                    const float* cp = mb + (size_t)(yy * WWp + xx) * CD;
                    float4 u0 = *(const float4*)(cp);
                    float4 u1 = *(const float4*)(cp + 4);
                    acc[0] += cw * u0.x; acc[1] += cw * u0.y;
                    acc[2] += cw * u0.z; acc[3] += cw * u0.w;
                    acc[4] += cw * u1.x; acc[5] += cw * u1.y;
                    acc[6] += cw * u1.z; acc[7] += cw * u1.w;
                    s += cw;
                }
            }
        }
    }

    float* urow = g_U + ((size_t)h * (NB * LQ) + bq) * CD + lane * 8;
    *(float4*)(urow)     = make_float4(acc[0], acc[1], acc[2], acc[3]);
    *(float4*)(urow + 4) = make_float4(acc[4], acc[5], acc[6], acc[7]);
    if (lane == 0) g_sw[(size_t)bq * NH + h] = s;
}

// ---------------- cp.async helpers ------------------------------------------
__device__ __forceinline__ void cpasync16(void* smem_dst, const void* gmem_src) {
    unsigned int s = (unsigned int)__cvta_generic_to_shared(smem_dst);
    asm volatile("cp.async.cg.shared.global [%0], [%1], 16;" :: "r"(s), "l"(gmem_src));
}
__device__ __forceinline__ void cpasync_commit() {
    asm volatile("cp.async.commit_group;");
}
__device__ __forceinline__ void cpasync_wait0() {
    asm volatile("cp.async.wait_group 0;");
}

// =====================================================================
// kernel 3: per-head value projection on gathered rows (TF32 wmma)
// sampled[bq][h*32+c] = U[h][bq][:] @ Wv[:, h*32+c] + s[bq][h]*bv[h*32+c]
// grid (64 m-blocks, 8 heads); BM=128, BN=32, BK=16, 2-stage cp.async
// =====================================================================
#define SBM 128
#define SBN 32
#define SBK 16
#define SLDA 20
#define SLDB 36
#define SLDC 36

struct __align__(16) SmemS {
    union {
        struct { float a[2][SBM * SLDA]; float b[2][SBK * SLDB]; } ab;
        float c[SBM * SLDC];
    };
};

__global__ void __launch_bounds__(256)
k_gemmS(const float* __restrict__ Wv, const float* __restrict__ bv)
{
    __shared__ SmemS sm;
    int h   = blockIdx.y;
    int m0  = blockIdx.x * SBM;
    int tid = threadIdx.x;
    int warpId = tid >> 5;             // 8 warps; warp w -> rows [w*16, w*16+16)

    const float* A = g_U + (size_t)h * (NB * LQ) * CD;

    wmma::fragment<wmma::accumulator, 16, 16, 8, float> acc[2];
    wmma::fill_fragment(acc[0], 0.0f);
    wmma::fill_fragment(acc[1], 0.0f);

    auto load_tiles = [&](int buf, int k0) {
        // A: 128x16 = 512 f4, 2 per thread
        #pragma unroll
        for (int i = 0; i < 2; i++) {
            int f4 = tid + i * 256;
            int r = f4 >> 2, c4 = f4 & 3;
            cpasync16(&sm.ab.a[buf][r * SLDA + c4 * 4],
                      A + (size_t)(m0 + r) * CD + k0 + c4 * 4);
        }
        // B: 16x32 = 128 f4, tid<128
        if (tid < 128) {
            int r = tid >> 3, c4 = tid & 7;
            cpasync16(&sm.ab.b[buf][r * SLDB + c4 * 4],
                      Wv + (size_t)(k0 + r) * CD + h * 32 + c4 * 4);
        }
        cpasync_commit();
    };

    load_tiles(0, 0);

    const int NIT = CD / SBK;          // 16
    for (int it = 0; it < NIT; ++it) {
        cpasync_wait0();
        __syncthreads();
        if (it + 1 < NIT) load_tiles((it + 1) & 1, (it + 1) * SBK);

        int buf = it & 1;
        #pragma unroll
        for (int kk = 0; kk < SBK; kk += 8) {
            wmma::fragment<wmma::matrix_a, 16, 16, 8, wmma::precision::tf32, wmma::row_major> af;
            wmma::fragment<wmma::matrix_b, 16, 16, 8, wmma::precision::tf32, wmma::row_major> bf[2];
            wmma::load_matrix_sync(af, &sm.ab.a[buf][(warpId * 16) * SLDA + kk], SLDA);
            #pragma unroll
            for (int e = 0; e < af.num_elements; e++)
                af.x[e] = wmma::__float_to_tf32(af.x[e]);
            #pragma unroll
            for (int j = 0; j < 2; j++) {
                wmma::load_matrix_sync(bf[j], &sm.ab.b[buf][kk * SLDB + j * 16], SLDB);
                #pragma unroll
                for (int e = 0; e < bf[j].num_elements; e++)
                    bf[j].x[e] = wmma::__float_to_tf32(bf[j].x[e]);
                wmma::mma_sync(acc[j], af, bf[j], acc[j]);
            }
        }
        __syncthreads();
    }

    #pragma unroll
    for (int j = 0; j < 2; j++)
        wmma::store_matrix_sync(&sm.c[(warpId * 16) * SLDC + j * 16], acc[j],
                                SLDC, wmma::mem_row_major);
    __syncthreads();

    // epilogue: 128x32 = 1024 f4, 4 per thread; add s*bv
    #pragma unroll
    for (int i = 0; i < 4; i++) {
        int f4 = i * 256 + tid;
        int r = f4 >> 3, c4 = f4 & 7;
        float s = g_sw[(size_t)(m0 + r) * NH + h];
        float4 v  = *(float4*)&sm.c[r * SLDC + c4 * 4];
        float4 bb = *(const float4*)(bv + h * 32 + c4 * 4);
        v.x += s * bb.x; v.y += s * bb.y; v.z += s * bb.z; v.w += s * bb.w;
        *(float4*)&g_S[(size_t)(m0 + r) * CD + h * 32 + c4 * 4] = v;
    }
}

// =====================================================================
// kernel 4: output projection GEMM (unchanged from passing R9 kernel)
// out[8192,256] = g_S @ Wout + bout; BM=128, BN=64, BK=16, 3 stages
// =====================================================================
#define BM 128
#define BN 64
#define BK 16
#define NSTG 3
#define LDA 20
#define LDB 68
#define LDC 68

struct __align__(16) SmemGemm {
    union {
        struct { float a[NSTG][BM * LDA]; float b[NSTG][BK * LDB]; } ab;
        float c[BM * LDC];
    };
};

__global__ void __launch_bounds__(256)
k_gemmO(const float* __restrict__ Wt, const float* __restrict__ bias,
        float* __restrict__ out)
{
    __shared__ SmemGemm sm;
    const float* A = (const float*)g_S;

    int n0 = blockIdx.x * BN;
    int m0 = blockIdx.y * BM;
    int tid = threadIdx.x;
    int warpId = tid >> 5;
    int wr = warpId >> 1;
    int wc = warpId & 1;

    wmma::fragment<wmma::accumulator, 16, 16, 8, float> acc[2][2];
    #pragma unroll
    for (int i = 0; i < 2; i++)
        #pragma unroll
        for (int j = 0; j < 2; j++) wmma::fill_fragment(acc[i][j], 0.0f);

    auto load_tiles = [&](int buf, int k0) {
        #pragma unroll
        for (int i = 0; i < 2; i++) {
            int f4 = tid + i * 256;
            int r = f4 >> 2, c4 = f4 & 3;
            cpasync16(&sm.ab.a[buf][r * LDA + c4 * 4],
                      A + (size_t)(m0 + r) * CD + k0 + c4 * 4);
        }
        {
            int r = tid >> 4, c4 = tid & 15;
            cpasync16(&sm.ab.b[buf][r * LDB + c4 * 4],
                      Wt + (size_t)(k0 + r) * CD + n0 + c4 * 4);
        }
        cpasync_commit();
    };

    load_tiles(0, 0);
    load_tiles(1, BK);

    const int NIT = CD / BK;
    for (int it = 0; it < NIT; ++it) {
        asm volatile("cp.async.wait_group 1;");
        __syncthreads();
        if (it + 2 < NIT) load_tiles((it + 2) % NSTG, (it + 2) * BK);
        else              cpasync_commit();

        int buf = it % NSTG;
        #pragma unroll
        for (int kk = 0; kk < BK; kk += 8) {
            wmma::fragment<wmma::matrix_a, 16, 16, 8, wmma::precision::tf32, wmma::row_major> af[2];
            wmma::fragment<wmma::matrix_b, 16, 16, 8, wmma::precision::tf32, wmma::row_major> bf[2];
            #pragma unroll
            for (int i = 0; i < 2; i++) {
                wmma::load_matrix_sync(af[i], &sm.ab.a[buf][(wr * 32 + i * 16) * LDA + kk], LDA);
                #pragma unroll
                for (int e = 0; e < af[i].num_elements; e++)
                    af[i].x[e] = wmma::__float_to_tf32(af[i].x[e]);
            }
            #pragma unroll
            for (int j = 0; j < 2; j++) {
                wmma::load_matrix_sync(bf[j], &sm.ab.b[buf][kk * LDB + wc * 32 + j * 16], LDB);
                #pragma unroll
                for (int e = 0; e < bf[j].num_elements; e++)
                    bf[j].x[e] = wmma::__float_to_tf32(bf[j].x[e]);
            }
            #pragma unroll
            for (int i = 0; i < 2; i++)
                #pragma unroll
                for (int j = 0; j < 2; j++)
                    wmma::mma_sync(acc[i][j], af[i], bf[j], acc[i][j]);
        }
        __syncthreads();
    }

    #pragma unroll
    for (int i = 0; i < 2; i++)
        #pragma unroll
        for (int j = 0; j < 2; j++)
            wmma::store_matrix_sync(&sm.c[(wr * 32 + i * 16) * LDC + wc * 32 + j * 16],
                                    acc[i][j], LDC, wmma::mem_row_major);
    __syncthreads();

    #pragma unroll
    for (int i = 0; i < 8; i++) {
        int id = i * 256 + tid;
        int r = id >> 4, c4 = id & 15;
        float4 v = *(float4*)&sm.c[r * LDC + c4 * 4];
        int col = n0 + c4 * 4;
        v.x += bias[col]; v.y += bias[col + 1]; v.z += bias[col + 2]; v.w += bias[col + 3];
        *(float4*)&out[(size_t)(m0 + r) * CD + col] = v;
    }
}

// ---------------- launch -----------------------------------------------------
extern "C" void kernel_launch(void* const* d_in, const int* in_sizes, int n_in,
                              void* d_out, int out_size)
{
    const float* query  = (const float*)d_in[0];
    const float* memory = (const float*)d_in[1];
    const float* refp   = (const float*)d_in[2];
    const float* Wv     = (const float*)d_in[3];
    const float* bv     = (const float*)d_in[4];
    const float* Woff   = (const float*)d_in[5];
    const float* boff   = (const float*)d_in[6];
    const float* Wattn  = (const float*)d_in[7];
    const float* battn  = (const float*)d_in[8];
    const float* Wout   = (const float*)d_in[9];
    const float* bout   = (const float*)d_in[10];
    float* out = (float*)d_out;

    // 1) offsets / attn weights / sample coordinates
    k_offsets<<<(NB * LQ) / QB, 256>>>(query, refp, Woff, boff, Wattn, battn);

    // 2) weighted gather of raw memory rows (sampling before projection)
    k_gather<<<NB * LQ, 256>>>(memory);

    // 3) per-head value projection on gathered rows (+ s*bv bias term)
    k_gemmS<<<dim3((NB * LQ) / SBM, NH), 256>>>(Wv, bv);

    // 4) output projection GEMM
    k_gemmO<<<dim3(CD / BN, (NB * LQ) / BM), 256>>>(Wout, bout, out);
}